// round 2
// baseline (speedup 1.0000x reference)
#include <cuda_runtime.h>
#include <cstdint>

#define FULL_MASK 0xffffffffu

constexpr int N = 64;
constexpr int WARPS_PER_BLOCK = 2;
constexpr int MAX_SWEEPS = 14;

// One warp per matrix.
// 1) Cholesky X = L L^T in shared memory (warp-cooperative).
// 2) One-sided Hestenes Jacobi on columns of L (Brent-Luk ring, 63-cycle):
//    H = L V = U Sigma, lambda_k = ||h_k||^2  (high relative accuracy).
// 3) Y = sum_k (log lambda_k / lambda_k) h_k h_k^T.
__global__ void __launch_bounds__(WARPS_PER_BLOCK * 32)
logeig_kernel(const float* __restrict__ X, float* __restrict__ Y, int nmat)
{
    __shared__ float Gs[WARPS_PER_BLOCK][N][N + 1];
    __shared__ float Ws[WARPS_PER_BLOCK][N];

    const int warp = threadIdx.x >> 5;
    const int lane = threadIdx.x & 31;
    const int mat  = blockIdx.x * WARPS_PER_BLOCK + warp;
    if (mat >= nmat) return;

    const float* Xm = X + (size_t)mat * N * N;

    // ---- Load X into shared (coalesced 256B rows) ----
#pragma unroll
    for (int i = 0; i < N; i++) {
        float2 v = *reinterpret_cast<const float2*>(Xm + i * N + 2 * lane);
        Gs[warp][i][2 * lane]     = v.x;
        Gs[warp][i][2 * lane + 1] = v.y;
    }
    __syncwarp();

    // ---- Cholesky (lower), in place ----
#pragma unroll 1
    for (int k = 0; k < N; k++) {
        float d    = sqrtf(Gs[warp][k][k]);
        float dinv = 1.0f / d;
        for (int i = k + 1 + lane; i < N; i += 32)
            Gs[warp][i][k] *= dinv;
        if (lane == 0) Gs[warp][k][k] = d;
        __syncwarp();
        for (int j = k + 1 + lane; j < N; j += 32) {
            float ljk = Gs[warp][j][k];
#pragma unroll 4
            for (int i = j; i < N; i++)
                Gs[warp][i][j] = fmaf(-Gs[warp][i][k], ljk, Gs[warp][i][j]);
        }
        __syncwarp();
    }

    // ---- Pull columns of L into registers (zero above diagonal) ----
    float x[N], y[N];
    const int c0i = 2 * lane, c1i = 2 * lane + 1;
#pragma unroll
    for (int i = 0; i < N; i++) {
        x[i] = (i >= c0i) ? Gs[warp][i][c0i] : 0.f;
        y[i] = (i >= c1i) ? Gs[warp][i][c1i] : 0.f;
    }
    __syncwarp();

    // Carried squared column norms.
    float nx = 0.f, ny = 0.f;
#pragma unroll
    for (int i = 0; i < N; i++) {
        nx = fmaf(x[i], x[i], nx);
        ny = fmaf(y[i], y[i], ny);
    }

    const bool lane0  = (lane == 0);
    const bool lane31 = (lane == 31);

    // ---- One-sided Jacobi sweeps ----
#pragma unroll 1
    for (int sweep = 0; sweep < MAX_SWEEPS; sweep++) {
        bool any_rot = false;
#pragma unroll 1
        for (int round = 0; round < 63; round++) {
            // g = x . y  (4 accumulators for ILP)
            float g0 = 0.f, g1 = 0.f, g2 = 0.f, g3 = 0.f;
#pragma unroll
            for (int i = 0; i < N; i += 4) {
                g0 = fmaf(x[i],     y[i],     g0);
                g1 = fmaf(x[i + 1], y[i + 1], g1);
                g2 = fmaf(x[i + 2], y[i + 2], g2);
                g3 = fmaf(x[i + 3], y[i + 3], g3);
            }
            float g = (g0 + g1) + (g2 + g3);

            const bool rot = (g * g > 1e-10f * nx * ny);
            any_rot |= rot;
            if (rot) {
                float zeta = (ny - nx) / (2.0f * g);
                float t = copysignf(1.0f / (fabsf(zeta) + sqrtf(fmaf(zeta, zeta, 1.0f))), zeta);
                float c = rsqrtf(fmaf(t, t, 1.0f));
                float s = c * t;
#pragma unroll
                for (int i = 0; i < N; i++) {
                    float xv = x[i], yv = y[i];
                    x[i] = fmaf(c, xv, -s * yv);
                    y[i] = fmaf(s, xv,  c * yv);
                }
                nx = fmaf(-t, g, nx);
                ny = fmaf( t, g, ny);
            }

            // Ring permutation (63-cycle, slot x0 fixed):
            //   new x[t] = t==0 ? x[t] : (t==31 ? y[t] : x[t+1])
            //   new y[t] = t==0 ? x[1] : y[t-1]
#pragma unroll
            for (int i = 0; i < N; i++) {
                float xv = x[i], yv = y[i];
                float xd = __shfl_down_sync(FULL_MASK, xv, 1);
                float yu = __shfl_up_sync(FULL_MASK, yv, 1);
                x[i] = lane0 ? xv : (lane31 ? yv : xd);
                y[i] = lane0 ? xd : yu;
            }
            {
                float xv = nx, yv = ny;
                float xd = __shfl_down_sync(FULL_MASK, xv, 1);
                float yu = __shfl_up_sync(FULL_MASK, yv, 1);
                nx = lane0 ? xv : (lane31 ? yv : xd);
                ny = lane0 ? xd : yu;
            }
        }
        if (!__any_sync(FULL_MASK, any_rot)) break;
    }

    // ---- Exact final norms: lambda = ||h||^2 ----
    {
        float a0 = 0.f, a1 = 0.f, b0 = 0.f, b1 = 0.f;
#pragma unroll
        for (int i = 0; i < N; i += 2) {
            a0 = fmaf(x[i],     x[i],     a0);
            a1 = fmaf(x[i + 1], x[i + 1], a1);
            b0 = fmaf(y[i],     y[i],     b0);
            b1 = fmaf(y[i + 1], y[i + 1], b1);
        }
        nx = a0 + a1;
        ny = b0 + b1;
    }
    // w_k = log(lambda_k) / lambda_k
    float wx = logf(nx) / nx;
    float wy = logf(ny) / ny;

    // ---- Stash H columns + weights; rank-64 reconstruction ----
    {
        float* c0 = &Gs[warp][c0i][0];
        float* c1 = &Gs[warp][c1i][0];
#pragma unroll
        for (int i = 0; i < N; i++) { c0[i] = x[i]; c1[i] = y[i]; }
        Ws[warp][c0i] = wx;
        Ws[warp][c1i] = wy;
    }
    __syncwarp();

#pragma unroll
    for (int i = 0; i < N; i++) { x[i] = 0.f; y[i] = 0.f; }

    const int j0 = lane, j1 = lane + 32;
#pragma unroll 2
    for (int k = 0; k < N; k++) {
        float w  = Ws[warp][k];
        float a0 = w * Gs[warp][k][j0];   // stride-1 across lanes
        float a1 = w * Gs[warp][k][j1];
#pragma unroll
        for (int i = 0; i < N; i++) {
            float b = Gs[warp][k][i];     // broadcast
            x[i] = fmaf(a0, b, x[i]);
            y[i] = fmaf(a1, b, y[i]);
        }
    }

    float* Ym = Y + (size_t)mat * N * N;
#pragma unroll
    for (int i = 0; i < N; i++) {
        Ym[i * N + j0] = x[i];   // coalesced
        Ym[i * N + j1] = y[i];
    }
}

extern "C" void kernel_launch(void* const* d_in, const int* in_sizes, int n_in,
                              void* d_out, int out_size)
{
    const float* X = (const float*)d_in[0];
    float* Y = (float*)d_out;
    int nmat = in_sizes[0] / (N * N);
    int blocks = (nmat + WARPS_PER_BLOCK - 1) / WARPS_PER_BLOCK;
    logeig_kernel<<<blocks, WARPS_PER_BLOCK * 32>>>(X, Y, nmat);
}

// round 4
// speedup vs baseline: 1.4285x; 1.4285x over previous
#include <cuda_runtime.h>
#include <cstdint>

#define FULL_MASK 0xffffffffu
typedef unsigned long long ull;

constexpr int N = 64;
constexpr int WPB = 2;
constexpr int MAX_SWEEPS = 14;
constexpr int STR = 66;   // smem stride in floats (even -> 8B-aligned columns)

__device__ __forceinline__ ull pk2(float a, float b) {
    ull r; asm("mov.b64 %0, {%1,%2};" : "=l"(r) : "f"(a), "f"(b)); return r;
}
__device__ __forceinline__ void upk2(ull v, float& a, float& b) {
    asm("mov.b64 {%0,%1}, %2;" : "=f"(a), "=f"(b) : "l"(v));
}
__device__ __forceinline__ ull fma2(ull a, ull b, ull c) {
    ull r; asm("fma.rn.f32x2 %0,%1,%2,%3;" : "=l"(r) : "l"(a), "l"(b), "l"(c)); return r;
}
__device__ __forceinline__ ull mul2(ull a, ull b) {
    ull r; asm("mul.rn.f32x2 %0,%1,%2;" : "=l"(r) : "l"(a), "l"(b)); return r;
}
__device__ __forceinline__ ull add2(ull a, ull b) {
    ull r; asm("add.rn.f32x2 %0,%1,%2;" : "=l"(r) : "l"(a), "l"(b)); return r;
}
__device__ __forceinline__ float hsum2(ull v) { float a, b; upk2(v, a, b); return a + b; }

// One warp per matrix.
// 1) Cholesky X = L L^T (smem).
// 2) One-sided Jacobi on columns of L, recursive merge ordering:
//    level k: groups of g=32>>k lanes; x fixed, y rotates g rounds (all x-y cross
//    pairs), then split x-set/y-set into half groups and recurse. 63 rounds = all
//    2016 pairs. Exchange: 64 SHFL/round, no selects.
// 3) lambda_k = ||h_k||^2 ; Y = sum_k (log l_k / l_k) h_k h_k^T.
__global__ void __launch_bounds__(WPB * 32)
logeig_kernel(const float* __restrict__ X, float* __restrict__ Y, int nmat)
{
    __shared__ float S[WPB][N * STR + N];

    const int warp = threadIdx.x >> 5;
    const int lane = threadIdx.x & 31;
    const int mat  = blockIdx.x * WPB + warp;
    if (mat >= nmat) return;

    float* C  = &S[warp][0];
    float* wv = C + N * STR;

    const float* Xm = X + (size_t)mat * N * N;

    // ---- Load X (coalesced) ----
#pragma unroll
    for (int i = 0; i < N; i++) {
        float2 v = *reinterpret_cast<const float2*>(Xm + i * N + 2 * lane);
        C[i * STR + 2 * lane]     = v.x;
        C[i * STR + 2 * lane + 1] = v.y;
    }
    __syncwarp();

    // ---- Cholesky (lower), in place ----
#pragma unroll 1
    for (int k = 0; k < N; k++) {
        float d    = sqrtf(C[k * STR + k]);
        float dinv = 1.0f / d;
        for (int i = k + 1 + lane; i < N; i += 32)
            C[i * STR + k] *= dinv;
        if (lane == 0) C[k * STR + k] = d;   // write back sqrt pivot (R3 bug fix)
        __syncwarp();
        for (int j = k + 1 + lane; j < N; j += 32) {
            float ljk = C[j * STR + k];
#pragma unroll 4
            for (int i = j; i < N; i++)
                C[i * STR + j] = fmaf(-C[i * STR + k], ljk, C[i * STR + j]);
        }
        __syncwarp();
    }

    // ---- Extract columns 2*lane, 2*lane+1 of L into packed registers ----
    ull x[32], y[32];
    {
        const int c0 = 2 * lane, c1 = 2 * lane + 1;
#pragma unroll
        for (int j = 0; j < 32; j++) {
            int i0 = 2 * j, i1 = 2 * j + 1;
            float a0 = (i0 >= c0) ? C[i0 * STR + c0] : 0.f;
            float a1 = (i1 >= c0) ? C[i1 * STR + c0] : 0.f;
            float b0 = (i0 >= c1) ? C[i0 * STR + c1] : 0.f;
            float b1 = (i1 >= c1) ? C[i1 * STR + c1] : 0.f;
            x[j] = pk2(a0, a1);
            y[j] = pk2(b0, b1);
        }
    }
    __syncwarp();

    float na, nb;

    // ---- Jacobi sweeps ----
#pragma unroll 1
    for (int sweep = 0; sweep < MAX_SWEEPS; sweep++) {
        // exact norm refresh (kills drift so the exit test can fire)
        {
            ull a0 = 0, a1 = 0, b0 = 0, b1 = 0;
#pragma unroll
            for (int j = 0; j < 32; j += 2) {
                a0 = fma2(x[j], x[j], a0);     a1 = fma2(x[j + 1], x[j + 1], a1);
                b0 = fma2(y[j], y[j], b0);     b1 = fma2(y[j + 1], y[j + 1], b1);
            }
            na = hsum2(add2(a0, a1));
            nb = hsum2(add2(b0, b1));
        }

        bool any_rot = false;
#pragma unroll 1
        for (int k = 0; k < 6; k++) {
            const int g    = 32 >> k;
            const int lin  = lane & (g - 1);
            const int rsrc = (lane & ~(g - 1)) | ((lin + 1) & (g - 1));
#pragma unroll 1
            for (int r = 0; r < g; r++) {
                ull d0 = 0, d1 = 0, d2 = 0, d3 = 0;
#pragma unroll
                for (int j = 0; j < 32; j += 4) {
                    d0 = fma2(x[j],     y[j],     d0);
                    d1 = fma2(x[j + 1], y[j + 1], d1);
                    d2 = fma2(x[j + 2], y[j + 2], d2);
                    d3 = fma2(x[j + 3], y[j + 3], d3);
                }
                float gd = hsum2(add2(add2(d0, d1), add2(d2, d3)));

                bool rot = (gd * gd > 1e-10f * na * nb);
                any_rot |= rot;
                if (rot) {
                    float zeta = __fdividef(nb - na, 2.0f * gd);
                    float t = copysignf(
                        __fdividef(1.0f, fabsf(zeta) + sqrtf(fmaf(zeta, zeta, 1.0f))), zeta);
                    float c = rsqrtf(fmaf(t, t, 1.0f));
                    float s = c * t;
                    ull c2 = pk2(c, c), s2 = pk2(s, s), m2 = pk2(-s, -s);
#pragma unroll
                    for (int j = 0; j < 32; j++) {
                        ull u = x[j], v = y[j];
                        x[j] = fma2(c2, u, mul2(m2, v));
                        y[j] = fma2(c2, v, mul2(s2, u));
                    }
                    na = fmaf(-t, gd, na);
                    nb = fmaf( t, gd, nb);
                }
                if (r != g - 1) {
#pragma unroll
                    for (int j = 0; j < 32; j++)
                        y[j] = __shfl_sync(FULL_MASK, y[j], rsrc);
                    nb = __shfl_sync(FULL_MASK, nb, rsrc);
                }
            }
            if (g > 1) {
                const int  h    = g >> 1;
                const int  base = lane & ~(g - 1);
                const bool tx   = (lin < h);
                const int  sA   = base + (tx ? 2 * lin : 2 * lin - g);
                const int  sB   = sA + 1;
#pragma unroll
                for (int j = 0; j < 32; j++) {
                    ull ax = __shfl_sync(FULL_MASK, x[j], sA);
                    ull ay = __shfl_sync(FULL_MASK, y[j], sA);
                    ull bx = __shfl_sync(FULL_MASK, x[j], sB);
                    ull by = __shfl_sync(FULL_MASK, y[j], sB);
                    x[j] = tx ? ax : ay;
                    y[j] = tx ? bx : by;
                }
                float ax = __shfl_sync(FULL_MASK, na, sA);
                float ay = __shfl_sync(FULL_MASK, nb, sA);
                float bx = __shfl_sync(FULL_MASK, na, sB);
                float by = __shfl_sync(FULL_MASK, nb, sB);
                na = tx ? ax : ay;
                nb = tx ? bx : by;
            }
        }
        if (!__any_sync(FULL_MASK, any_rot)) break;
    }

    // ---- Exact eigenvalues + weights ----
    {
        ull a0 = 0, a1 = 0, b0 = 0, b1 = 0;
#pragma unroll
        for (int j = 0; j < 32; j += 2) {
            a0 = fma2(x[j], x[j], a0);     a1 = fma2(x[j + 1], x[j + 1], a1);
            b0 = fma2(y[j], y[j], b0);     b1 = fma2(y[j + 1], y[j + 1], b1);
        }
        na = hsum2(add2(a0, a1));
        nb = hsum2(add2(b0, b1));
    }
    float wx = logf(na) / na;
    float wy = logf(nb) / nb;

    // ---- Stash columns + weights (slot identity is irrelevant) ----
    __syncwarp();
    {
        ull* c0 = reinterpret_cast<ull*>(C + (2 * lane) * STR);
        ull* c1 = reinterpret_cast<ull*>(C + (2 * lane + 1) * STR);
#pragma unroll
        for (int j = 0; j < 32; j++) { c0[j] = x[j]; c1[j] = y[j]; }
        wv[2 * lane]     = wx;
        wv[2 * lane + 1] = wy;
    }
    __syncwarp();

    // ---- Y[i][j] = sum_k w_k H[i][k] H[j][k]; lane -> output cols lane, lane+32 ----
    ull accx[32], accy[32];
#pragma unroll
    for (int j = 0; j < 32; j++) { accx[j] = 0; accy[j] = 0; }

    const int j0 = lane, j1 = lane + 32;
#pragma unroll 1
    for (int k = 0; k < N; k++) {
        const float* ck = C + k * STR;
        float w  = wv[k];
        float a0 = w * ck[j0];
        float a1 = w * ck[j1];
        ull a02 = pk2(a0, a0), a12 = pk2(a1, a1);
        const ull* cp = reinterpret_cast<const ull*>(ck);
#pragma unroll
        for (int j = 0; j < 32; j++) {
            ull b = cp[j];                 // broadcast
            accx[j] = fma2(a02, b, accx[j]);
            accy[j] = fma2(a12, b, accy[j]);
        }
    }

    float* Ym = Y + (size_t)mat * N * N;
#pragma unroll
    for (int j = 0; j < 32; j++) {
        float lo, hi;
        upk2(accx[j], lo, hi);
        Ym[(2 * j) * N + j0]     = lo;
        Ym[(2 * j + 1) * N + j0] = hi;
        upk2(accy[j], lo, hi);
        Ym[(2 * j) * N + j1]     = lo;
        Ym[(2 * j + 1) * N + j1] = hi;
    }
}

extern "C" void kernel_launch(void* const* d_in, const int* in_sizes, int n_in,
                              void* d_out, int out_size)
{
    const float* X = (const float*)d_in[0];
    float* Y = (float*)d_out;
    int nmat = in_sizes[0] / (N * N);
    int blocks = (nmat + WPB - 1) / WPB;
    logeig_kernel<<<blocks, WPB * 32>>>(X, Y, nmat);
}

// round 5
// speedup vs baseline: 1.5584x; 1.0909x over previous
#include <cuda_runtime.h>
#include <cstdint>

#define FULL_MASK 0xffffffffu
typedef unsigned long long ull;

constexpr int N = 64;
constexpr int WPB = 2;
constexpr int MAX_SWEEPS = 14;
constexpr int STR = 66;   // smem stride in floats (even -> 8B-aligned columns)

__device__ __forceinline__ ull pk2(float a, float b) {
    ull r; asm("mov.b64 %0, {%1,%2};" : "=l"(r) : "f"(a), "f"(b)); return r;
}
__device__ __forceinline__ void upk2(ull v, float& a, float& b) {
    asm("mov.b64 {%0,%1}, %2;" : "=f"(a), "=f"(b) : "l"(v));
}
__device__ __forceinline__ ull fma2(ull a, ull b, ull c) {
    ull r; asm("fma.rn.f32x2 %0,%1,%2,%3;" : "=l"(r) : "l"(a), "l"(b), "l"(c)); return r;
}
__device__ __forceinline__ ull mul2(ull a, ull b) {
    ull r; asm("mul.rn.f32x2 %0,%1,%2;" : "=l"(r) : "l"(a), "l"(b)); return r;
}
__device__ __forceinline__ ull add2(ull a, ull b) {
    ull r; asm("add.rn.f32x2 %0,%1,%2;" : "=l"(r) : "l"(a), "l"(b)); return r;
}
__device__ __forceinline__ float hsum2(ull v) { float a, b; upk2(v, a, b); return a + b; }

// One warp per matrix.
// 1) Cholesky X = L L^T (smem).
// 2) One-sided Jacobi on columns of L, recursive merge ordering (63 rounds =
//    all 2016 pairs). Deferred-cosine rotations: column stored as sigma * h~,
//    rotation applies only tangent FMAs (1 fma2/elem/output), cosine folds
//    into sigma. Scales folded back into columns at each sweep-start refresh.
// 3) lambda_k = ||h_k||^2 ; Y = sum_k (log l_k / l_k) h_k h_k^T (sigma^2 in weight).
__global__ void __launch_bounds__(WPB * 32)
logeig_kernel(const float* __restrict__ X, float* __restrict__ Y, int nmat)
{
    __shared__ float S[WPB][N * STR + N];

    const int warp = threadIdx.x >> 5;
    const int lane = threadIdx.x & 31;
    const int mat  = blockIdx.x * WPB + warp;
    if (mat >= nmat) return;

    float* C  = &S[warp][0];
    float* wv = C + N * STR;

    const float* Xm = X + (size_t)mat * N * N;

    // ---- Load X (coalesced) ----
#pragma unroll
    for (int i = 0; i < N; i++) {
        float2 v = *reinterpret_cast<const float2*>(Xm + i * N + 2 * lane);
        C[i * STR + 2 * lane]     = v.x;
        C[i * STR + 2 * lane + 1] = v.y;
    }
    __syncwarp();

    // ---- Cholesky (lower), in place ----
#pragma unroll 1
    for (int k = 0; k < N; k++) {
        float d    = sqrtf(C[k * STR + k]);
        float dinv = 1.0f / d;
        for (int i = k + 1 + lane; i < N; i += 32)
            C[i * STR + k] *= dinv;
        if (lane == 0) C[k * STR + k] = d;
        __syncwarp();
        for (int j = k + 1 + lane; j < N; j += 32) {
            float ljk = C[j * STR + k];
#pragma unroll 4
            for (int i = j; i < N; i++)
                C[i * STR + j] = fmaf(-C[i * STR + k], ljk, C[i * STR + j]);
        }
        __syncwarp();
    }

    // ---- Extract columns 2*lane, 2*lane+1 of L into packed registers ----
    ull x[32], y[32];
    {
        const int c0 = 2 * lane, c1 = 2 * lane + 1;
#pragma unroll
        for (int j = 0; j < 32; j++) {
            int i0 = 2 * j, i1 = 2 * j + 1;
            float a0 = (i0 >= c0) ? C[i0 * STR + c0] : 0.f;
            float a1 = (i1 >= c0) ? C[i1 * STR + c0] : 0.f;
            float b0 = (i0 >= c1) ? C[i0 * STR + c1] : 0.f;
            float b1 = (i1 >= c1) ? C[i1 * STR + c1] : 0.f;
            x[j] = pk2(a0, a1);
            y[j] = pk2(b0, b1);
        }
    }
    __syncwarp();

    float na, nb;            // true squared norms
    float sx = 1.f, sy = 1.f; // deferred column scales (true col = s * stored col)

    // ---- Jacobi sweeps ----
#pragma unroll 1
    for (int sweep = 0; sweep < MAX_SWEEPS; sweep++) {
        // Fold scales back into columns; exact norm refresh.
        {
            ull sx2 = pk2(sx, sx), sy2 = pk2(sy, sy);
            ull a0 = 0, a1 = 0, b0 = 0, b1 = 0;
#pragma unroll
            for (int j = 0; j < 32; j += 2) {
                x[j]     = mul2(sx2, x[j]);
                x[j + 1] = mul2(sx2, x[j + 1]);
                y[j]     = mul2(sy2, y[j]);
                y[j + 1] = mul2(sy2, y[j + 1]);
                a0 = fma2(x[j], x[j], a0);     a1 = fma2(x[j + 1], x[j + 1], a1);
                b0 = fma2(y[j], y[j], b0);     b1 = fma2(y[j + 1], y[j + 1], b1);
            }
            na = hsum2(add2(a0, a1));
            nb = hsum2(add2(b0, b1));
            sx = 1.f; sy = 1.f;
        }

        bool any_rot = false;
#pragma unroll 1
        for (int k = 0; k < 6; k++) {
            const int g    = 32 >> k;
            const int lin  = lane & (g - 1);
            const int rsrc = (lane & ~(g - 1)) | ((lin + 1) & (g - 1));
#pragma unroll 1
            for (int r = 0; r < g; r++) {
                ull d0 = 0, d1 = 0, d2 = 0, d3 = 0;
#pragma unroll
                for (int j = 0; j < 32; j += 4) {
                    d0 = fma2(x[j],     y[j],     d0);
                    d1 = fma2(x[j + 1], y[j + 1], d1);
                    d2 = fma2(x[j + 2], y[j + 2], d2);
                    d3 = fma2(x[j + 3], y[j + 3], d3);
                }
                float gt = hsum2(add2(add2(d0, d1), add2(d2, d3)));
                float gd = (sx * sy) * gt;   // true dot

                bool rot = (gd * gd > 1e-9f * na * nb);
                any_rot |= rot;
                if (rot) {
                    float zeta = __fdividef(nb - na, 2.0f * gd);
                    float t = copysignf(
                        __fdividef(1.0f, fabsf(zeta) + sqrtf(fmaf(zeta, zeta, 1.0f))), zeta);
                    float c = rsqrtf(fmaf(t, t, 1.0f));
                    float tx = t * __fdividef(sy, sx);   // x~' = x~ - tx*y~
                    float ty = t * __fdividef(sx, sy);   // y~' = y~ + ty*x~(old)
                    sx *= c; sy *= c;
                    na = fmaf(-t, gd, na);
                    nb = fmaf( t, gd, nb);
                    ull mtx2 = pk2(-tx, -tx), ty2 = pk2(ty, ty);
#pragma unroll
                    for (int j = 0; j < 32; j++) {
                        ull u = x[j];
                        x[j] = fma2(mtx2, y[j], u);
                        y[j] = fma2(ty2, u, y[j]);
                    }
                }
                if (r != g - 1) {
#pragma unroll
                    for (int j = 0; j < 32; j++)
                        y[j] = __shfl_sync(FULL_MASK, y[j], rsrc);
                    nb = __shfl_sync(FULL_MASK, nb, rsrc);
                    sy = __shfl_sync(FULL_MASK, sy, rsrc);
                }
            }
            if (g > 1) {
                const int  h    = g >> 1;
                const int  base = lane & ~(g - 1);
                const bool tx_  = (lin < h);
                const int  sA   = base + (tx_ ? 2 * lin : 2 * lin - g);
                const int  sB   = sA + 1;
#pragma unroll
                for (int j = 0; j < 32; j++) {
                    ull ax = __shfl_sync(FULL_MASK, x[j], sA);
                    ull ay = __shfl_sync(FULL_MASK, y[j], sA);
                    ull bx = __shfl_sync(FULL_MASK, x[j], sB);
                    ull by = __shfl_sync(FULL_MASK, y[j], sB);
                    x[j] = tx_ ? ax : ay;
                    y[j] = tx_ ? bx : by;
                }
                float ax = __shfl_sync(FULL_MASK, na, sA);
                float ay = __shfl_sync(FULL_MASK, nb, sA);
                float bx = __shfl_sync(FULL_MASK, na, sB);
                float by = __shfl_sync(FULL_MASK, nb, sB);
                na = tx_ ? ax : ay;
                nb = tx_ ? bx : by;
                float px = __shfl_sync(FULL_MASK, sx, sA);
                float py = __shfl_sync(FULL_MASK, sy, sA);
                float qx = __shfl_sync(FULL_MASK, sx, sB);
                float qy = __shfl_sync(FULL_MASK, sy, sB);
                sx = tx_ ? px : py;
                sy = tx_ ? qx : qy;
            }
        }
        if (!__any_sync(FULL_MASK, any_rot)) break;
    }

    // ---- Exact eigenvalues + weights (fold sigma^2 into weight) ----
    {
        ull a0 = 0, a1 = 0, b0 = 0, b1 = 0;
#pragma unroll
        for (int j = 0; j < 32; j += 2) {
            a0 = fma2(x[j], x[j], a0);     a1 = fma2(x[j + 1], x[j + 1], a1);
            b0 = fma2(y[j], y[j], b0);     b1 = fma2(y[j + 1], y[j + 1], b1);
        }
        float s2x = hsum2(add2(a0, a1));
        float s2y = hsum2(add2(b0, b1));
        na = (sx * sx) * s2x;               // true lambda
        nb = (sy * sy) * s2y;
        // Y = sum (log l / l) h h^T, h = s * h~  =>  weight on h~ h~^T is s^2 log l / l
        float wx = (sx * sx) * logf(na) / na;
        float wy = (sy * sy) * logf(nb) / nb;

        __syncwarp();
        ull* c0 = reinterpret_cast<ull*>(C + (2 * lane) * STR);
        ull* c1 = reinterpret_cast<ull*>(C + (2 * lane + 1) * STR);
#pragma unroll
        for (int j = 0; j < 32; j++) { c0[j] = x[j]; c1[j] = y[j]; }
        wv[2 * lane]     = wx;
        wv[2 * lane + 1] = wy;
    }
    __syncwarp();

    // ---- Y[i][j] = sum_k w_k H~[i][k] H~[j][k]; lane -> output cols lane, lane+32 ----
    ull accx[32], accy[32];
#pragma unroll
    for (int j = 0; j < 32; j++) { accx[j] = 0; accy[j] = 0; }

    const int j0 = lane, j1 = lane + 32;
#pragma unroll 1
    for (int k = 0; k < N; k++) {
        const float* ck = C + k * STR;
        float w  = wv[k];
        float a0 = w * ck[j0];
        float a1 = w * ck[j1];
        ull a02 = pk2(a0, a0), a12 = pk2(a1, a1);
        const ull* cp = reinterpret_cast<const ull*>(ck);
#pragma unroll
        for (int j = 0; j < 32; j++) {
            ull b = cp[j];                 // broadcast
            accx[j] = fma2(a02, b, accx[j]);
            accy[j] = fma2(a12, b, accy[j]);
        }
    }

    float* Ym = Y + (size_t)mat * N * N;
#pragma unroll
    for (int j = 0; j < 32; j++) {
        float lo, hi;
        upk2(accx[j], lo, hi);
        Ym[(2 * j) * N + j0]     = lo;
        Ym[(2 * j + 1) * N + j0] = hi;
        upk2(accy[j], lo, hi);
        Ym[(2 * j) * N + j1]     = lo;
        Ym[(2 * j + 1) * N + j1] = hi;
    }
}

extern "C" void kernel_launch(void* const* d_in, const int* in_sizes, int n_in,
                              void* d_out, int out_size)
{
    const float* X = (const float*)d_in[0];
    float* Y = (float*)d_out;
    int nmat = in_sizes[0] / (N * N);
    int blocks = (nmat + WPB - 1) / WPB;
    logeig_kernel<<<blocks, WPB * 32>>>(X, Y, nmat);
}